// round 1
// baseline (speedup 1.0000x reference)
#include <cuda_runtime.h>
#include <cuda_bf16.h>
#include <math.h>

#define NN 50000
#define NE 800000

// ---------------- device scratch (no allocations allowed) ----------------
__device__ float4 g_buf0[NN * 16];   // gemm output (max N x 64 floats)
__device__ float4 g_buf1[NN * 16];   // agg output / layer activations
__device__ int    g_deg[NN];
__device__ float  g_dinv[NN];
__device__ int    g_rowptr[NN + 1];
__device__ int    g_cursor[NN];
__device__ int    g_colidx[NE];
__device__ float  g_val[NE];
__device__ float  g_cs[2][16];       // column sums of h3 per graph
__device__ float  g_cvec[16];        // attention context vector
__device__ float  g_evec[2][16];     // pooled embeddings

// ---------------- CSR build ----------------
__global__ void reset_kernel(int gi) {
    int stride = gridDim.x * blockDim.x;
    for (int i = blockIdx.x * blockDim.x + threadIdx.x; i < NN; i += stride)
        g_deg[i] = 0;
    if (blockIdx.x == 0 && threadIdx.x < 16) {
        g_cs[gi][threadIdx.x] = 0.f;
        g_evec[gi][threadIdx.x] = 0.f;
    }
}

__global__ void hist_kernel(const int* __restrict__ dst) {
    int e = blockIdx.x * blockDim.x + threadIdx.x;
    if (e < NE) atomicAdd(&g_deg[dst[e]], 1);
}

__global__ void dinv_kernel() {
    int n = blockIdx.x * blockDim.x + threadIdx.x;
    if (n < NN) g_dinv[n] = rsqrtf((float)g_deg[n] + 1.0f);
}

__global__ void scan_kernel() {
    __shared__ int sdata[1024];
    const int CH = 49;  // 49*1024 = 50176 >= NN
    int t = threadIdx.x;
    int base = t * CH;
    int s = 0;
    for (int i = 0; i < CH; i++) {
        int idx = base + i;
        if (idx < NN) s += g_deg[idx];
    }
    sdata[t] = s;
    __syncthreads();
    for (int off = 1; off < 1024; off <<= 1) {
        int v = (t >= off) ? sdata[t - off] : 0;
        __syncthreads();
        sdata[t] += v;
        __syncthreads();
    }
    int run = sdata[t] - s;  // exclusive prefix
    for (int i = 0; i < CH; i++) {
        int idx = base + i;
        if (idx < NN) {
            g_rowptr[idx] = run;
            g_cursor[idx] = run;
            run += g_deg[idx];
        }
    }
    if (t == 1023) g_rowptr[NN] = run;
}

__global__ void scatter_kernel(const int* __restrict__ src, const int* __restrict__ dst) {
    int e = blockIdx.x * blockDim.x + threadIdx.x;
    if (e < NE) {
        int s = src[e], d = dst[e];
        int pos = atomicAdd(&g_cursor[d], 1);
        g_colidx[pos] = s;
        g_val[pos] = g_dinv[s] * g_dinv[d];
    }
}

// ---------------- dense GEMM: out(g_buf0) = X @ W  (X: [NN,K], W: [K,C]) ----------------
template <int K, int C, bool FROMBUF>
__global__ void gemm_kernel(const float* __restrict__ Xext, const float* __restrict__ W) {
    constexpr int TC = 4;             // cols per thread
    constexpr int CT = C / TC;        // col-thread count
    constexpr int RT = 256 / CT;      // row-thread count
    constexpr int TR = 8;             // rows per thread
    constexpr int TILE = RT * TR;     // rows per block
    constexpr int KC = 16;
    __shared__ __align__(16) float Ws[KC][C];
    __shared__ float Xs[KC][TILE + 1];

    const float* X = FROMBUF ? (const float*)g_buf1 : Xext;
    int row0 = blockIdx.x * TILE;
    int t = threadIdx.x;
    int ct = t % CT, rt = t / CT;

    float acc[TR][TC];
#pragma unroll
    for (int i = 0; i < TR; i++)
#pragma unroll
        for (int j = 0; j < TC; j++) acc[i][j] = 0.f;

    for (int k0 = 0; k0 < K; k0 += KC) {
        for (int i = t; i < KC * C; i += 256)
            Ws[i / C][i % C] = W[(k0 + i / C) * C + (i % C)];
        for (int i = t; i < TILE * KC; i += 256) {
            int r = i >> 4, kk = i & 15;
            int gr = row0 + r;
            Xs[kk][r] = (gr < NN) ? X[gr * K + k0 + kk] : 0.f;
        }
        __syncthreads();
#pragma unroll
        for (int kk = 0; kk < KC; kk++) {
            float4 wv = *(const float4*)&Ws[kk][ct * TC];
#pragma unroll
            for (int i = 0; i < TR; i++) {
                float xv = Xs[kk][rt * TR + i];
                acc[i][0] += xv * wv.x;
                acc[i][1] += xv * wv.y;
                acc[i][2] += xv * wv.z;
                acc[i][3] += xv * wv.w;
            }
        }
        __syncthreads();
    }
    float* out = (float*)g_buf0;
#pragma unroll
    for (int i = 0; i < TR; i++) {
        int gr = row0 + rt * TR + i;
        if (gr < NN) {
            float4 v = make_float4(acc[i][0], acc[i][1], acc[i][2], acc[i][3]);
            *(float4*)&out[gr * C + ct * TC] = v;
        }
    }
}

// ---------------- CSR aggregation: g_buf1 = relu?(segsum + selfloop + b) ----------------
template <int C, bool RELU>
__global__ void agg_kernel(const float* __restrict__ b) {
    constexpr int LPN = C / 4;  // float4 lanes per node
    int tid = blockIdx.x * blockDim.x + threadIdx.x;
    int node = tid / LPN;
    int chunk = tid - node * LPN;
    if (node >= NN) return;
    int s = g_rowptr[node], e = g_rowptr[node + 1];
    const float4* h4 = (const float4*)g_buf0;
    float4 acc = make_float4(0.f, 0.f, 0.f, 0.f);
    for (int i = s; i < e; i++) {
        int c = g_colidx[i];
        float v = g_val[i];
        float4 hv = h4[c * LPN + chunk];
        acc.x += v * hv.x;
        acc.y += v * hv.y;
        acc.z += v * hv.z;
        acc.w += v * hv.w;
    }
    float dv = g_dinv[node];
    float d2 = dv * dv;
    float4 hs = h4[node * LPN + chunk];
    float4 bb = ((const float4*)b)[chunk];
    acc.x += d2 * hs.x + bb.x;
    acc.y += d2 * hs.y + bb.y;
    acc.z += d2 * hs.z + bb.z;
    acc.w += d2 * hs.w + bb.w;
    if (RELU) {
        acc.x = fmaxf(acc.x, 0.f);
        acc.y = fmaxf(acc.y, 0.f);
        acc.z = fmaxf(acc.z, 0.f);
        acc.w = fmaxf(acc.w, 0.f);
    }
    ((float4*)g_buf1)[node * LPN + chunk] = acc;
}

// ---------------- attention pooling ----------------
__global__ void colsum_kernel(int gi) {
    __shared__ float acc[16];
    int t = threadIdx.x;
    if (t < 16) acc[t] = 0.f;
    __syncthreads();
    float la[16];
#pragma unroll
    for (int j = 0; j < 16; j++) la[j] = 0.f;
    for (int n = blockIdx.x * blockDim.x + t; n < NN; n += gridDim.x * blockDim.x) {
        const float4* h4 = g_buf1 + n * 4;
#pragma unroll
        for (int j = 0; j < 4; j++) {
            float4 v = h4[j];
            la[4 * j + 0] += v.x;
            la[4 * j + 1] += v.y;
            la[4 * j + 2] += v.z;
            la[4 * j + 3] += v.w;
        }
    }
#pragma unroll
    for (int j = 0; j < 16; j++) atomicAdd(&acc[j], la[j]);
    __syncthreads();
    if (t < 16) atomicAdd(&g_cs[gi][t], acc[t]);
}

__global__ void cvec_kernel(const float* __restrict__ Wa, int gi) {
    int j = threadIdx.x;
    if (j < 16) {
        float a = 0.f;
        for (int i = 0; i < 16; i++) a += g_cs[gi][i] * Wa[i * 16 + j];
        g_cvec[j] = tanhf(a * (1.0f / (float)NN));
    }
}

__global__ void pool_kernel(int gi) {
    __shared__ float csh[16];
    __shared__ float acc[16];
    int t = threadIdx.x;
    if (t < 16) {
        csh[t] = g_cvec[t];
        acc[t] = 0.f;
    }
    __syncthreads();
    float la[16];
#pragma unroll
    for (int j = 0; j < 16; j++) la[j] = 0.f;
    for (int n = blockIdx.x * blockDim.x + t; n < NN; n += gridDim.x * blockDim.x) {
        const float4* h4 = g_buf1 + n * 4;
        float hv[16];
#pragma unroll
        for (int j = 0; j < 4; j++) {
            float4 v = h4[j];
            hv[4 * j + 0] = v.x;
            hv[4 * j + 1] = v.y;
            hv[4 * j + 2] = v.z;
            hv[4 * j + 3] = v.w;
        }
        float dot = 0.f;
#pragma unroll
        for (int j = 0; j < 16; j++) dot += hv[j] * csh[j];
        float sg = 1.f / (1.f + __expf(-dot));
#pragma unroll
        for (int j = 0; j < 16; j++) la[j] += sg * hv[j];
    }
#pragma unroll
    for (int j = 0; j < 16; j++) atomicAdd(&acc[j], la[j]);
    __syncthreads();
    if (t < 16) atomicAdd(&g_evec[gi][t], acc[t]);
}

// ---------------- NTN + MLP tail ----------------
__global__ void final_kernel(const float* __restrict__ Wt, const float* __restrict__ Wb,
                             const float* __restrict__ bt, const float* __restrict__ Wfc,
                             const float* __restrict__ bfc, const float* __restrict__ Wsc,
                             const float* __restrict__ bsc, float* __restrict__ out) {
    __shared__ float tsh[16], s2[16];
    int k = threadIdx.x;
    if (k < 16) {
        float bil = 0.f;
        for (int i = 0; i < 16; i++) {
            float e1v = g_evec[0][i];
            for (int j = 0; j < 16; j++)
                bil += e1v * Wt[(i * 16 + j) * 16 + k] * g_evec[1][j];
        }
        float blk = 0.f;
        for (int j = 0; j < 16; j++)
            blk += Wb[k * 32 + j] * g_evec[0][j] + Wb[k * 32 + 16 + j] * g_evec[1][j];
        float v = bil + blk + bt[k];
        tsh[k] = v > 0.f ? v : 0.f;
    }
    __syncthreads();
    if (k < 16) {
        float a = bfc[k];
        for (int j = 0; j < 16; j++) a += tsh[j] * Wfc[j * 16 + k];
        s2[k] = tanhf(a);
    }
    __syncthreads();
    if (k == 0) {
        float a = bsc[0];
        for (int j = 0; j < 16; j++) a += s2[j] * Wsc[j];
        out[0] = 1.f / (1.f + expf(-a));
    }
}

// ---------------- launch ----------------
extern "C" void kernel_launch(void* const* d_in, const int* in_sizes, int n_in,
                              void* d_out, int out_size) {
    const float* X1  = (const float*)d_in[0];
    const float* X2  = (const float*)d_in[1];
    const int*   E1  = (const int*)d_in[2];
    const int*   E2  = (const int*)d_in[3];
    const float* W1  = (const float*)d_in[4];
    const float* b1  = (const float*)d_in[5];
    const float* W2  = (const float*)d_in[6];
    const float* b2  = (const float*)d_in[7];
    const float* W3  = (const float*)d_in[8];
    const float* b3  = (const float*)d_in[9];
    const float* Wa  = (const float*)d_in[10];
    const float* Wt  = (const float*)d_in[11];
    const float* Wb  = (const float*)d_in[12];
    const float* bt  = (const float*)d_in[13];
    const float* Wfc = (const float*)d_in[14];
    const float* bfc = (const float*)d_in[15];
    const float* Wsc = (const float*)d_in[16];
    const float* bsc = (const float*)d_in[17];
    float* out = (float*)d_out;

    const int EB = (NE + 255) / 256;
    const int NB = (NN + 255) / 256;

    for (int gi = 0; gi < 2; gi++) {
        const float* X = gi ? X2 : X1;
        const int* Eg = gi ? E2 : E1;
        const int* src = Eg;
        const int* dst = Eg + NE;

        reset_kernel<<<98, 512>>>(gi);
        hist_kernel<<<EB, 256>>>(dst);
        dinv_kernel<<<NB, 256>>>();
        scan_kernel<<<1, 1024>>>();
        scatter_kernel<<<EB, 256>>>(src, dst);

        // layer 1: 96 -> 64 (relu)
        gemm_kernel<96, 64, false><<<(NN + 127) / 128, 256>>>(X, W1);
        agg_kernel<64, true><<<(NN * 16 + 255) / 256, 256>>>(b1);
        // layer 2: 64 -> 32 (relu)
        gemm_kernel<64, 32, true><<<(NN + 255) / 256, 256>>>(nullptr, W2);
        agg_kernel<32, true><<<(NN * 8 + 255) / 256, 256>>>(b2);
        // layer 3: 32 -> 16 (no relu)
        gemm_kernel<32, 16, true><<<(NN + 511) / 512, 256>>>(nullptr, W3);
        agg_kernel<16, false><<<(NN * 4 + 255) / 256, 256>>>(b3);

        colsum_kernel<<<256, 256>>>(gi);
        cvec_kernel<<<1, 32>>>(Wa, gi);
        pool_kernel<<<256, 256>>>(gi);
    }
    final_kernel<<<1, 32>>>(Wt, Wb, bt, Wfc, bfc, Wsc, bsc, out);
}

// round 2
// speedup vs baseline: 1.7630x; 1.7630x over previous
#include <cuda_runtime.h>
#include <cuda_bf16.h>
#include <math.h>

#define NN 50000
#define NE 800000
#define NBLK 196   // ceil(NN/256)

// ---------------- device scratch (no allocations allowed) ----------------
__device__ float g_h[2][NN * 64];     // gemm output per graph
__device__ float g_a[2][NN * 64];     // agg output per graph
__device__ int   g_deg[2][NN];
__device__ float g_dinv[2][NN];
__device__ int   g_rowptr[2][NN + 1];
__device__ int   g_cursor[2][NN];
__device__ int   g_colidx[2][NE];
__device__ float g_val[2][NE];
__device__ int   g_bsum[2][NBLK];
__device__ float g_cs[2][16];
__device__ float g_cvec[2][16];
__device__ float g_evec[2][16];

// ---------------- reset ----------------
__global__ void reset_kernel() {
    int stride = gridDim.x * blockDim.x;
    for (int i = blockIdx.x * blockDim.x + threadIdx.x; i < 2 * NN; i += stride) {
        int gi = i < NN ? 0 : 1;
        int n = i < NN ? i : i - NN;
        g_deg[gi][n] = 0;
    }
    if (blockIdx.x == 0 && threadIdx.x < 32) {
        int gi = threadIdx.x >> 4, j = threadIdx.x & 15;
        g_cs[gi][j] = 0.f;
        g_evec[gi][j] = 0.f;
    }
}

// ---------------- histogram (in-degree) ----------------
__global__ void hist_kernel(const int* __restrict__ E1, const int* __restrict__ E2) {
    int gi = blockIdx.y;
    const int* dst = (gi ? E2 : E1) + NE;
    int e = blockIdx.x * blockDim.x + threadIdx.x;
    if (e < NE) atomicAdd(&g_deg[gi][dst[e]], 1);
}

__global__ void dinv_kernel() {
    int gi = blockIdx.y;
    int n = blockIdx.x * blockDim.x + threadIdx.x;
    if (n < NN) g_dinv[gi][n] = rsqrtf((float)g_deg[gi][n] + 1.0f);
}

// ---------------- 2-phase scan ----------------
__global__ void scanA_kernel() {
    int gi = blockIdx.y;
    int bid = blockIdx.x;
    int t = threadIdx.x;
    int idx = bid * 256 + t;
    int v = (idx < NN) ? g_deg[gi][idx] : 0;
    int lane = t & 31, wid = t >> 5;
    // warp inclusive scan
    int s = v;
#pragma unroll
    for (int off = 1; off < 32; off <<= 1) {
        int u = __shfl_up_sync(0xffffffffu, s, off);
        if (lane >= off) s += u;
    }
    __shared__ int wsum[8];
    if (lane == 31) wsum[wid] = s;
    __syncthreads();
    if (t < 8) {
        int ws = wsum[t];
#pragma unroll
        for (int off = 1; off < 8; off <<= 1) {
            int u = __shfl_up_sync(0xffu, ws, off);
            if ((t & 7) >= off) ws += u;
        }
        wsum[t] = ws;
    }
    __syncthreads();
    int wpre = wid ? wsum[wid - 1] : 0;
    int excl = wpre + s - v;              // block-local exclusive prefix
    if (idx < NN) g_rowptr[gi][idx] = excl;
    if (t == 255) g_bsum[gi][bid] = wpre + s;  // block total
}

__global__ void scanC_kernel() {
    int gi = blockIdx.y;
    int bid = blockIdx.x;
    int t = threadIdx.x;
    __shared__ int sd[256];
    sd[t] = (t < bid) ? g_bsum[gi][t] : 0;
    __syncthreads();
    for (int off = 128; off > 0; off >>= 1) {
        if (t < off) sd[t] += sd[t + off];
        __syncthreads();
    }
    int offset = sd[0];
    int idx = bid * 256 + t;
    if (idx < NN) {
        int r = g_rowptr[gi][idx] + offset;
        g_rowptr[gi][idx] = r;
        g_cursor[gi][idx] = r;
    }
    if (bid == 0 && t == 0) g_rowptr[gi][NN] = NE;
}

// ---------------- scatter into CSR ----------------
__global__ void scatter_kernel(const int* __restrict__ E1, const int* __restrict__ E2) {
    int gi = blockIdx.y;
    const int* Eg = gi ? E2 : E1;
    const int* src = Eg;
    const int* dst = Eg + NE;
    int e = blockIdx.x * blockDim.x + threadIdx.x;
    if (e < NE) {
        int s = src[e], d = dst[e];
        int pos = atomicAdd(&g_cursor[gi][d], 1);
        g_colidx[gi][pos] = s;
        g_val[gi][pos] = g_dinv[gi][s] * g_dinv[gi][d];
    }
}

// ---------------- dense GEMM: g_h[gi] = X @ W ----------------
template <int K, int C, bool FROMBUF>
__global__ void gemm_kernel(const float* __restrict__ X1, const float* __restrict__ X2,
                            const float* __restrict__ W) {
    constexpr int TC = 4;
    constexpr int CT = C / TC;
    constexpr int RT = 256 / CT;
    constexpr int TR = 8;
    constexpr int TILE = RT * TR;
    constexpr int KC = 16;
    __shared__ __align__(16) float Ws[KC][C];
    __shared__ float Xs[KC][TILE + 1];

    int gi = blockIdx.y;
    const float* X = FROMBUF ? g_a[gi] : (gi ? X2 : X1);
    int row0 = blockIdx.x * TILE;
    int t = threadIdx.x;
    int ct = t % CT, rt = t / CT;

    float acc[TR][TC];
#pragma unroll
    for (int i = 0; i < TR; i++)
#pragma unroll
        for (int j = 0; j < TC; j++) acc[i][j] = 0.f;

    for (int k0 = 0; k0 < K; k0 += KC) {
        for (int i = t; i < KC * C; i += 256)
            Ws[i / C][i % C] = W[(k0 + i / C) * C + (i % C)];
        for (int i = t; i < TILE * KC; i += 256) {
            int r = i >> 4, kk = i & 15;
            int gr = row0 + r;
            Xs[kk][r] = (gr < NN) ? X[gr * K + k0 + kk] : 0.f;
        }
        __syncthreads();
#pragma unroll
        for (int kk = 0; kk < KC; kk++) {
            float4 wv = *(const float4*)&Ws[kk][ct * TC];
#pragma unroll
            for (int i = 0; i < TR; i++) {
                float xv = Xs[kk][rt * TR + i];
                acc[i][0] += xv * wv.x;
                acc[i][1] += xv * wv.y;
                acc[i][2] += xv * wv.z;
                acc[i][3] += xv * wv.w;
            }
        }
        __syncthreads();
    }
    float* out = g_h[gi];
#pragma unroll
    for (int i = 0; i < TR; i++) {
        int gr = row0 + rt * TR + i;
        if (gr < NN) {
            float4 v = make_float4(acc[i][0], acc[i][1], acc[i][2], acc[i][3]);
            *(float4*)&out[gr * C + ct * TC] = v;
        }
    }
}

// ---------------- CSR aggregation ----------------
template <int C, bool RELU>
__global__ void agg_kernel(const float* __restrict__ b) {
    constexpr int LPN = C / 4;
    int gi = blockIdx.y;
    int tid = blockIdx.x * blockDim.x + threadIdx.x;
    int node = tid / LPN;
    int chunk = tid - node * LPN;
    if (node >= NN) return;
    int s = g_rowptr[gi][node], e = g_rowptr[gi][node + 1];
    const float4* h4 = (const float4*)g_h[gi];
    const int* ci = g_colidx[gi];
    const float* cv = g_val[gi];
    float4 acc = make_float4(0.f, 0.f, 0.f, 0.f);
    for (int i = s; i < e; i++) {
        int c = ci[i];
        float v = cv[i];
        float4 hv = h4[c * LPN + chunk];
        acc.x += v * hv.x;
        acc.y += v * hv.y;
        acc.z += v * hv.z;
        acc.w += v * hv.w;
    }
    float dv = g_dinv[gi][node];
    float d2 = dv * dv;
    float4 hs = h4[node * LPN + chunk];
    float4 bb = ((const float4*)b)[chunk];
    acc.x += d2 * hs.x + bb.x;
    acc.y += d2 * hs.y + bb.y;
    acc.z += d2 * hs.z + bb.z;
    acc.w += d2 * hs.w + bb.w;
    if (RELU) {
        acc.x = fmaxf(acc.x, 0.f);
        acc.y = fmaxf(acc.y, 0.f);
        acc.z = fmaxf(acc.z, 0.f);
        acc.w = fmaxf(acc.w, 0.f);
    }
    ((float4*)g_a[gi])[node * LPN + chunk] = acc;
}

// ---------------- attention pooling ----------------
__global__ void colsum_kernel() {
    int gi = blockIdx.y;
    __shared__ float acc[16];
    int t = threadIdx.x;
    if (t < 16) acc[t] = 0.f;
    __syncthreads();
    float la[16];
#pragma unroll
    for (int j = 0; j < 16; j++) la[j] = 0.f;
    const float4* base = (const float4*)g_a[gi];
    for (int n = blockIdx.x * blockDim.x + t; n < NN; n += gridDim.x * blockDim.x) {
        const float4* h4 = base + n * 4;
#pragma unroll
        for (int j = 0; j < 4; j++) {
            float4 v = h4[j];
            la[4 * j + 0] += v.x;
            la[4 * j + 1] += v.y;
            la[4 * j + 2] += v.z;
            la[4 * j + 3] += v.w;
        }
    }
#pragma unroll
    for (int j = 0; j < 16; j++) atomicAdd(&acc[j], la[j]);
    __syncthreads();
    if (t < 16) atomicAdd(&g_cs[gi][t], acc[t]);
}

__global__ void cvec_kernel(const float* __restrict__ Wa) {
    int gi = blockIdx.x;
    int j = threadIdx.x;
    if (j < 16) {
        float a = 0.f;
        for (int i = 0; i < 16; i++) a += g_cs[gi][i] * Wa[i * 16 + j];
        g_cvec[gi][j] = tanhf(a * (1.0f / (float)NN));
    }
}

__global__ void pool_kernel() {
    int gi = blockIdx.y;
    __shared__ float csh[16];
    __shared__ float acc[16];
    int t = threadIdx.x;
    if (t < 16) {
        csh[t] = g_cvec[gi][t];
        acc[t] = 0.f;
    }
    __syncthreads();
    float la[16];
#pragma unroll
    for (int j = 0; j < 16; j++) la[j] = 0.f;
    const float4* base = (const float4*)g_a[gi];
    for (int n = blockIdx.x * blockDim.x + t; n < NN; n += gridDim.x * blockDim.x) {
        const float4* h4 = base + n * 4;
        float hv[16];
#pragma unroll
        for (int j = 0; j < 4; j++) {
            float4 v = h4[j];
            hv[4 * j + 0] = v.x;
            hv[4 * j + 1] = v.y;
            hv[4 * j + 2] = v.z;
            hv[4 * j + 3] = v.w;
        }
        float dot = 0.f;
#pragma unroll
        for (int j = 0; j < 16; j++) dot += hv[j] * csh[j];
        float sg = 1.f / (1.f + __expf(-dot));
#pragma unroll
        for (int j = 0; j < 16; j++) la[j] += sg * hv[j];
    }
#pragma unroll
    for (int j = 0; j < 16; j++) atomicAdd(&acc[j], la[j]);
    __syncthreads();
    if (t < 16) atomicAdd(&g_evec[gi][t], acc[t]);
}

// ---------------- NTN + MLP tail ----------------
__global__ void final_kernel(const float* __restrict__ Wt, const float* __restrict__ Wb,
                             const float* __restrict__ bt, const float* __restrict__ Wfc,
                             const float* __restrict__ bfc, const float* __restrict__ Wsc,
                             const float* __restrict__ bsc, float* __restrict__ out) {
    __shared__ float tsh[16], s2[16];
    int k = threadIdx.x;
    if (k < 16) {
        float bil = 0.f;
        for (int i = 0; i < 16; i++) {
            float e1v = g_evec[0][i];
            for (int j = 0; j < 16; j++)
                bil += e1v * Wt[(i * 16 + j) * 16 + k] * g_evec[1][j];
        }
        float blk = 0.f;
        for (int j = 0; j < 16; j++)
            blk += Wb[k * 32 + j] * g_evec[0][j] + Wb[k * 32 + 16 + j] * g_evec[1][j];
        float v = bil + blk + bt[k];
        tsh[k] = v > 0.f ? v : 0.f;
    }
    __syncthreads();
    if (k < 16) {
        float a = bfc[k];
        for (int j = 0; j < 16; j++) a += tsh[j] * Wfc[j * 16 + k];
        s2[k] = tanhf(a);
    }
    __syncthreads();
    if (k == 0) {
        float a = bsc[0];
        for (int j = 0; j < 16; j++) a += s2[j] * Wsc[j];
        out[0] = 1.f / (1.f + expf(-a));
    }
}

// ---------------- launch ----------------
extern "C" void kernel_launch(void* const* d_in, const int* in_sizes, int n_in,
                              void* d_out, int out_size) {
    const float* X1  = (const float*)d_in[0];
    const float* X2  = (const float*)d_in[1];
    const int*   E1  = (const int*)d_in[2];
    const int*   E2  = (const int*)d_in[3];
    const float* W1  = (const float*)d_in[4];
    const float* b1  = (const float*)d_in[5];
    const float* W2  = (const float*)d_in[6];
    const float* b2  = (const float*)d_in[7];
    const float* W3  = (const float*)d_in[8];
    const float* b3  = (const float*)d_in[9];
    const float* Wa  = (const float*)d_in[10];
    const float* Wt  = (const float*)d_in[11];
    const float* Wb  = (const float*)d_in[12];
    const float* bt  = (const float*)d_in[13];
    const float* Wfc = (const float*)d_in[14];
    const float* bfc = (const float*)d_in[15];
    const float* Wsc = (const float*)d_in[16];
    const float* bsc = (const float*)d_in[17];
    float* out = (float*)d_out;

    const int EB = (NE + 255) / 256;
    const int NB = (NN + 255) / 256;

    reset_kernel<<<148, 512>>>();
    hist_kernel<<<dim3(EB, 2), 256>>>(E1, E2);
    dinv_kernel<<<dim3(NB, 2), 256>>>();
    scanA_kernel<<<dim3(NBLK, 2), 256>>>();
    scanC_kernel<<<dim3(NBLK, 2), 256>>>();
    scatter_kernel<<<dim3(EB, 2), 256>>>(E1, E2);

    // layer 1: 96 -> 64 (relu): TILE=128
    gemm_kernel<96, 64, false><<<dim3((NN + 127) / 128, 2), 256>>>(X1, X2, W1);
    agg_kernel<64, true><<<dim3((NN * 16 + 255) / 256, 2), 256>>>(b1);
    // layer 2: 64 -> 32 (relu): TILE=256
    gemm_kernel<64, 32, true><<<dim3((NN + 255) / 256, 2), 256>>>(nullptr, nullptr, W2);
    agg_kernel<32, true><<<dim3((NN * 8 + 255) / 256, 2), 256>>>(b2);
    // layer 3: 32 -> 16 (no relu): TILE=512
    gemm_kernel<32, 16, true><<<dim3((NN + 511) / 512, 2), 256>>>(nullptr, nullptr, W3);
    agg_kernel<16, false><<<dim3((NN * 4 + 255) / 256, 2), 256>>>(b3);

    colsum_kernel<<<dim3(128, 2), 256>>>();
    cvec_kernel<<<2, 32>>>(Wa);
    pool_kernel<<<dim3(128, 2), 256>>>();
    final_kernel<<<1, 32>>>(Wt, Wb, bt, Wfc, bfc, Wsc, bsc, out);
}

// round 3
// speedup vs baseline: 2.0094x; 1.1397x over previous
#include <cuda_runtime.h>
#include <cuda_bf16.h>
#include <math.h>

#define NN 50000
#define NE 800000
#define NBLK 196   // ceil(NN/256)

// ---------------- device scratch ----------------
__device__ float g_h[2][NN * 64];
__device__ float g_a[2][NN * 64];
__device__ int   g_deg[2][NN];
__device__ float g_dinv[2][NN];
__device__ int   g_rowptr[2][NN + 1];
__device__ int   g_cursor[2][NN];
__device__ int   g_colidx[2][NE];
__device__ float g_val[2][NE];
__device__ int   g_bsum[2][NBLK];
__device__ float g_cs[2][16];
__device__ float g_evec[2][16];

// ---------------- reset ----------------
__global__ void reset_kernel() {
    int stride = gridDim.x * blockDim.x;
    for (int i = blockIdx.x * blockDim.x + threadIdx.x; i < 2 * NN; i += stride) {
        int gi = i < NN ? 0 : 1;
        int n = i < NN ? i : i - NN;
        g_deg[gi][n] = 0;
    }
    if (blockIdx.x == 0 && threadIdx.x < 32) {
        int gi = threadIdx.x >> 4, j = threadIdx.x & 15;
        g_cs[gi][j] = 0.f;
        g_evec[gi][j] = 0.f;
    }
}

// ---------------- histogram (in-degree), int4 edges ----------------
__global__ void hist_kernel(const int* __restrict__ E1, const int* __restrict__ E2) {
    int gi = blockIdx.y;
    const int4* dst = (const int4*)((gi ? E2 : E1) + NE);
    int e4 = blockIdx.x * blockDim.x + threadIdx.x;
    if (e4 < NE / 4) {
        int4 d = dst[e4];
        atomicAdd(&g_deg[gi][d.x], 1);
        atomicAdd(&g_deg[gi][d.y], 1);
        atomicAdd(&g_deg[gi][d.z], 1);
        atomicAdd(&g_deg[gi][d.w], 1);
    }
}

// ---------------- scan phase A (+ dinv fused) ----------------
__global__ void scanA_kernel() {
    int gi = blockIdx.y;
    int bid = blockIdx.x;
    int t = threadIdx.x;
    int idx = bid * 256 + t;
    int v = (idx < NN) ? g_deg[gi][idx] : 0;
    if (idx < NN) g_dinv[gi][idx] = rsqrtf((float)v + 1.0f);
    int lane = t & 31, wid = t >> 5;
    int s = v;
#pragma unroll
    for (int off = 1; off < 32; off <<= 1) {
        int u = __shfl_up_sync(0xffffffffu, s, off);
        if (lane >= off) s += u;
    }
    __shared__ int wsum[8];
    if (lane == 31) wsum[wid] = s;
    __syncthreads();
    if (t < 8) {
        int ws = wsum[t];
#pragma unroll
        for (int off = 1; off < 8; off <<= 1) {
            int u = __shfl_up_sync(0xffu, ws, off);
            if ((t & 7) >= off) ws += u;
        }
        wsum[t] = ws;
    }
    __syncthreads();
    int wpre = wid ? wsum[wid - 1] : 0;
    int excl = wpre + s - v;
    if (idx < NN) g_rowptr[gi][idx] = excl;
    if (t == 255) g_bsum[gi][bid] = wpre + s;
}

__global__ void scanC_kernel() {
    int gi = blockIdx.y;
    int bid = blockIdx.x;
    int t = threadIdx.x;
    __shared__ int sd[256];
    sd[t] = (t < bid) ? g_bsum[gi][t] : 0;
    __syncthreads();
    for (int off = 128; off > 0; off >>= 1) {
        if (t < off) sd[t] += sd[t + off];
        __syncthreads();
    }
    int offset = sd[0];
    int idx = bid * 256 + t;
    if (idx < NN) {
        int r = g_rowptr[gi][idx] + offset;
        g_rowptr[gi][idx] = r;
        g_cursor[gi][idx] = r;
    }
    if (bid == 0 && t == 0) g_rowptr[gi][NN] = NE;
}

// ---------------- scatter into CSR, int4 edges ----------------
__global__ void scatter_kernel(const int* __restrict__ E1, const int* __restrict__ E2) {
    int gi = blockIdx.y;
    const int* Eg = gi ? E2 : E1;
    const int4* src = (const int4*)Eg;
    const int4* dst = (const int4*)(Eg + NE);
    int e4 = blockIdx.x * blockDim.x + threadIdx.x;
    if (e4 < NE / 4) {
        int4 sv = src[e4];
        int4 dv = dst[e4];
        const float* di = g_dinv[gi];
        int* ci = g_colidx[gi];
        float* cv = g_val[gi];
        int* cur = g_cursor[gi];
        {
            int pos = atomicAdd(&cur[dv.x], 1);
            ci[pos] = sv.x; cv[pos] = di[sv.x] * di[dv.x];
        }
        {
            int pos = atomicAdd(&cur[dv.y], 1);
            ci[pos] = sv.y; cv[pos] = di[sv.y] * di[dv.y];
        }
        {
            int pos = atomicAdd(&cur[dv.z], 1);
            ci[pos] = sv.z; cv[pos] = di[sv.z] * di[dv.z];
        }
        {
            int pos = atomicAdd(&cur[dv.w], 1);
            ci[pos] = sv.w; cv[pos] = di[sv.w] * di[dv.w];
        }
    }
}

// ---------------- dense GEMM: g_h[gi] = X @ W ----------------
// NH column-halves of 4 cols each per thread; TR rows per thread; 256 threads.
template <int K, int C, int NH, int TR, bool FROMBUF>
__global__ void gemm_kernel(const float* __restrict__ X1, const float* __restrict__ X2,
                            const float* __restrict__ W) {
    constexpr int CT = C / (4 * NH);
    constexpr int RT = 256 / CT;
    constexpr int TILE = RT * TR;
    constexpr int KC = 16;
    constexpr int XSTR = TILE + 4;
    constexpr int HW = C / NH;
    __shared__ __align__(16) float Ws[KC][C];
    __shared__ __align__(16) float Xs[KC][XSTR];

    int gi = blockIdx.y;
    const float* X = FROMBUF ? g_a[gi] : (gi ? X2 : X1);
    int row0 = blockIdx.x * TILE;
    int t = threadIdx.x;
    int ct = t % CT, rt = t / CT;

    float acc[TR][4 * NH];
#pragma unroll
    for (int i = 0; i < TR; i++)
#pragma unroll
        for (int j = 0; j < 4 * NH; j++) acc[i][j] = 0.f;

    for (int k0 = 0; k0 < K; k0 += KC) {
        for (int i = t; i < KC * C; i += 256)
            Ws[i / C][i % C] = W[(k0 + i / C) * C + (i % C)];
        for (int i = t; i < TILE * KC; i += 256) {
            int r = i >> 4, kk = i & 15;
            int gr = row0 + r;
            Xs[kk][r] = (gr < NN) ? X[gr * K + k0 + kk] : 0.f;
        }
        __syncthreads();
#pragma unroll
        for (int kk = 0; kk < KC; kk++) {
            float w[4 * NH];
#pragma unroll
            for (int h = 0; h < NH; h++)
                *(float4*)&w[4 * h] = *(const float4*)&Ws[kk][h * HW + ct * 4];
            float x[TR];
#pragma unroll
            for (int i = 0; i < TR; i += 4)
                *(float4*)&x[i] = *(const float4*)&Xs[kk][rt * TR + i];
#pragma unroll
            for (int i = 0; i < TR; i++)
#pragma unroll
                for (int j = 0; j < 4 * NH; j++)
                    acc[i][j] += x[i] * w[j];
        }
        __syncthreads();
    }
    float* out = g_h[gi];
#pragma unroll
    for (int i = 0; i < TR; i++) {
        int gr = row0 + rt * TR + i;
        if (gr < NN) {
#pragma unroll
            for (int h = 0; h < NH; h++) {
                float4 v = make_float4(acc[i][4 * h], acc[i][4 * h + 1],
                                       acc[i][4 * h + 2], acc[i][4 * h + 3]);
                *(float4*)&out[gr * C + h * HW + ct * 4] = v;
            }
        }
    }
}

// ---------------- CSR aggregation (C=64/32), dual-chain MLP ----------------
template <int C, bool RELU>
__global__ void agg_kernel(const float* __restrict__ b) {
    constexpr int LPN = C / 4;
    int gi = blockIdx.y;
    int tid = blockIdx.x * blockDim.x + threadIdx.x;
    int node = tid / LPN;
    int chunk = tid - node * LPN;
    if (node >= NN) return;
    int s = g_rowptr[gi][node], e = g_rowptr[gi][node + 1];
    const float4* h4 = (const float4*)g_h[gi];
    const int* ci = g_colidx[gi];
    const float* cv = g_val[gi];
    float4 a0 = make_float4(0.f, 0.f, 0.f, 0.f);
    float4 a1 = make_float4(0.f, 0.f, 0.f, 0.f);
    int i = s;
    for (; i + 1 < e; i += 2) {
        int c0 = ci[i], c1 = ci[i + 1];
        float v0 = cv[i], v1 = cv[i + 1];
        float4 h0 = h4[c0 * LPN + chunk];
        float4 h1 = h4[c1 * LPN + chunk];
        a0.x += v0 * h0.x; a0.y += v0 * h0.y; a0.z += v0 * h0.z; a0.w += v0 * h0.w;
        a1.x += v1 * h1.x; a1.y += v1 * h1.y; a1.z += v1 * h1.z; a1.w += v1 * h1.w;
    }
    if (i < e) {
        int c0 = ci[i];
        float v0 = cv[i];
        float4 h0 = h4[c0 * LPN + chunk];
        a0.x += v0 * h0.x; a0.y += v0 * h0.y; a0.z += v0 * h0.z; a0.w += v0 * h0.w;
    }
    a0.x += a1.x; a0.y += a1.y; a0.z += a1.z; a0.w += a1.w;
    float dv = g_dinv[gi][node];
    float d2 = dv * dv;
    float4 hs = h4[node * LPN + chunk];
    float4 bb = ((const float4*)b)[chunk];
    a0.x += d2 * hs.x + bb.x;
    a0.y += d2 * hs.y + bb.y;
    a0.z += d2 * hs.z + bb.z;
    a0.w += d2 * hs.w + bb.w;
    if (RELU) {
        a0.x = fmaxf(a0.x, 0.f);
        a0.y = fmaxf(a0.y, 0.f);
        a0.z = fmaxf(a0.z, 0.f);
        a0.w = fmaxf(a0.w, 0.f);
    }
    ((float4*)g_a[gi])[node * LPN + chunk] = a0;
}

// ---------------- layer-3 aggregation (C=16) + column-sum fusion ----------------
__global__ void agg16_kernel(const float* __restrict__ b) {
    int gi = blockIdx.y;
    __shared__ float cssh[16];
    int t = threadIdx.x;
    if (t < 16) cssh[t] = 0.f;
    __syncthreads();
    int tid = blockIdx.x * 256 + t;
    int node = tid >> 2;
    int chunk = tid & 3;
    if (node < NN) {
        int s = g_rowptr[gi][node], e = g_rowptr[gi][node + 1];
        const float4* h4 = (const float4*)g_h[gi];
        const int* ci = g_colidx[gi];
        const float* cv = g_val[gi];
        float4 a0 = make_float4(0.f, 0.f, 0.f, 0.f);
        float4 a1 = make_float4(0.f, 0.f, 0.f, 0.f);
        int i = s;
        for (; i + 1 < e; i += 2) {
            int c0 = ci[i], c1 = ci[i + 1];
            float v0 = cv[i], v1 = cv[i + 1];
            float4 h0 = h4[c0 * 4 + chunk];
            float4 h1 = h4[c1 * 4 + chunk];
            a0.x += v0 * h0.x; a0.y += v0 * h0.y; a0.z += v0 * h0.z; a0.w += v0 * h0.w;
            a1.x += v1 * h1.x; a1.y += v1 * h1.y; a1.z += v1 * h1.z; a1.w += v1 * h1.w;
        }
        if (i < e) {
            int c0 = ci[i];
            float v0 = cv[i];
            float4 h0 = h4[c0 * 4 + chunk];
            a0.x += v0 * h0.x; a0.y += v0 * h0.y; a0.z += v0 * h0.z; a0.w += v0 * h0.w;
        }
        a0.x += a1.x; a0.y += a1.y; a0.z += a1.z; a0.w += a1.w;
        float dv = g_dinv[gi][node];
        float d2 = dv * dv;
        float4 hs = h4[node * 4 + chunk];
        float4 bb = ((const float4*)b)[chunk];
        a0.x += d2 * hs.x + bb.x;
        a0.y += d2 * hs.y + bb.y;
        a0.z += d2 * hs.z + bb.z;
        a0.w += d2 * hs.w + bb.w;
        ((float4*)g_a[gi])[node * 4 + chunk] = a0;
        atomicAdd(&cssh[chunk * 4 + 0], a0.x);
        atomicAdd(&cssh[chunk * 4 + 1], a0.y);
        atomicAdd(&cssh[chunk * 4 + 2], a0.z);
        atomicAdd(&cssh[chunk * 4 + 3], a0.w);
    }
    __syncthreads();
    if (t < 16) atomicAdd(&g_cs[gi][t], cssh[t]);
}

// ---------------- attention pooling (cvec fused) ----------------
__global__ void pool_kernel(const float* __restrict__ Wa) {
    int gi = blockIdx.y;
    __shared__ float csh[16];
    __shared__ float acc[16];
    int t = threadIdx.x;
    if (t < 16) {
        float a = 0.f;
        for (int i = 0; i < 16; i++) a += g_cs[gi][i] * Wa[i * 16 + t];
        csh[t] = tanhf(a * (1.0f / (float)NN));
        acc[t] = 0.f;
    }
    __syncthreads();
    float la[16];
#pragma unroll
    for (int j = 0; j < 16; j++) la[j] = 0.f;
    const float4* base = (const float4*)g_a[gi];
    for (int n = blockIdx.x * blockDim.x + t; n < NN; n += gridDim.x * blockDim.x) {
        const float4* h4 = base + n * 4;
        float hv[16];
#pragma unroll
        for (int j = 0; j < 4; j++) {
            float4 v = h4[j];
            hv[4 * j + 0] = v.x;
            hv[4 * j + 1] = v.y;
            hv[4 * j + 2] = v.z;
            hv[4 * j + 3] = v.w;
        }
        float dot = 0.f;
#pragma unroll
        for (int j = 0; j < 16; j++) dot += hv[j] * csh[j];
        float sg = 1.f / (1.f + __expf(-dot));
#pragma unroll
        for (int j = 0; j < 16; j++) la[j] += sg * hv[j];
    }
#pragma unroll
    for (int j = 0; j < 16; j++) atomicAdd(&acc[j], la[j]);
    __syncthreads();
    if (t < 16) atomicAdd(&g_evec[gi][t], acc[t]);
}

// ---------------- NTN + MLP tail ----------------
__global__ void final_kernel(const float* __restrict__ Wt, const float* __restrict__ Wb,
                             const float* __restrict__ bt, const float* __restrict__ Wfc,
                             const float* __restrict__ bfc, const float* __restrict__ Wsc,
                             const float* __restrict__ bsc, float* __restrict__ out) {
    __shared__ float tsh[16], s2[16];
    int k = threadIdx.x;
    if (k < 16) {
        float bil = 0.f;
        for (int i = 0; i < 16; i++) {
            float e1v = g_evec[0][i];
            for (int j = 0; j < 16; j++)
                bil += e1v * Wt[(i * 16 + j) * 16 + k] * g_evec[1][j];
        }
        float blk = 0.f;
        for (int j = 0; j < 16; j++)
            blk += Wb[k * 32 + j] * g_evec[0][j] + Wb[k * 32 + 16 + j] * g_evec[1][j];
        float v = bil + blk + bt[k];
        tsh[k] = v > 0.f ? v : 0.f;
    }
    __syncthreads();
    if (k < 16) {
        float a = bfc[k];
        for (int j = 0; j < 16; j++) a += tsh[j] * Wfc[j * 16 + k];
        s2[k] = tanhf(a);
    }
    __syncthreads();
    if (k == 0) {
        float a = bsc[0];
        for (int j = 0; j < 16; j++) a += s2[j] * Wsc[j];
        out[0] = 1.f / (1.f + expf(-a));
    }
}

// ---------------- launch ----------------
extern "C" void kernel_launch(void* const* d_in, const int* in_sizes, int n_in,
                              void* d_out, int out_size) {
    const float* X1  = (const float*)d_in[0];
    const float* X2  = (const float*)d_in[1];
    const int*   E1  = (const int*)d_in[2];
    const int*   E2  = (const int*)d_in[3];
    const float* W1  = (const float*)d_in[4];
    const float* b1  = (const float*)d_in[5];
    const float* W2  = (const float*)d_in[6];
    const float* b2  = (const float*)d_in[7];
    const float* W3  = (const float*)d_in[8];
    const float* b3  = (const float*)d_in[9];
    const float* Wa  = (const float*)d_in[10];
    const float* Wt  = (const float*)d_in[11];
    const float* Wb  = (const float*)d_in[12];
    const float* bt  = (const float*)d_in[13];
    const float* Wfc = (const float*)d_in[14];
    const float* bfc = (const float*)d_in[15];
    const float* Wsc = (const float*)d_in[16];
    const float* bsc = (const float*)d_in[17];
    float* out = (float*)d_out;

    const int E4B = (NE / 4 + 255) / 256;   // 782

    reset_kernel<<<148, 512>>>();
    hist_kernel<<<dim3(E4B, 2), 256>>>(E1, E2);
    scanA_kernel<<<dim3(NBLK, 2), 256>>>();
    scanC_kernel<<<dim3(NBLK, 2), 256>>>();
    scatter_kernel<<<dim3(E4B, 2), 256>>>(E1, E2);

    // layer 1: 96 -> 64 (relu), TILE=256
    gemm_kernel<96, 64, 2, 8, false><<<dim3((NN + 255) / 256, 2), 256>>>(X1, X2, W1);
    agg_kernel<64, true><<<dim3((NN * 16 + 255) / 256, 2), 256>>>(b1);
    // layer 2: 64 -> 32 (relu), TILE=256
    gemm_kernel<64, 32, 2, 4, true><<<dim3((NN + 255) / 256, 2), 256>>>(nullptr, nullptr, W2);
    agg_kernel<32, true><<<dim3((NN * 8 + 255) / 256, 2), 256>>>(b2);
    // layer 3: 32 -> 16 (no relu), TILE=256, colsum fused
    gemm_kernel<32, 16, 1, 4, true><<<dim3((NN + 255) / 256, 2), 256>>>(nullptr, nullptr, W3);
    agg16_kernel<<<dim3((NN * 4 + 255) / 256, 2), 256>>>(b3);

    pool_kernel<<<dim3(128, 2), 256>>>(Wa);
    final_kernel<<<1, 32>>>(Wt, Wb, bt, Wfc, bfc, Wsc, bsc, out);
}